// round 3
// baseline (speedup 1.0000x reference)
#include <cuda_runtime.h>
#include <cstdint>

// Haar 3D, stride-2, 2x2x2 depthwise, 8 filters per channel.
// x: [N=2, C=16, D=128, H=128, W=128] fp32
// y: [N=2, C*8=128, D2=64, H2=64, W2=64] fp32
//
// One thread processes TWO adjacent 2x2x2 blocks along W:
//   loads:  4 x float4  (2 depth planes x 2 rows x 4 consecutive w)
//   stores: 8 x float2  (one per Haar output channel)
// Filter o = a*4 + b*2 + c (a: depth bit, b: height bit, c: width bit),
// y_o = 0.125 * sum_{ijk} (-1)^(a*i + b*j + c*k) v[i][j][k]  -- pure butterfly.

#define C_IN   16
#define D_IN   128
#define H_IN   128
#define W_IN   128
#define D2     64
#define H2     64
#define W2     64

__global__ __launch_bounds__(256) void haar3d_kernel(
    const float* __restrict__ x, float* __restrict__ y)
{
    const int w4  = threadIdx.x;                            // 0..31 (covers 2 w-blocks = 4 floats)
    const int h2  = blockIdx.y * blockDim.y + threadIdx.y;  // 0..63
    const int ncd = blockIdx.x;                             // n*C*D2 flat
    const int d2  = ncd & 63;
    const int nc  = ncd >> 6;                               // n*C + c

    // Input base: x[n][c][2*d2][2*h2][4*w4]
    const float* xin = x
        + ((size_t)nc * D_IN + 2 * d2) * (size_t)(H_IN * W_IN)
        + (size_t)(2 * h2) * W_IN
        + 4 * w4;

    // 4 vectorized loads: (d0,h0) (d0,h1) (d1,h0) (d1,h1)
    const float4 a00 = *reinterpret_cast<const float4*>(xin);
    const float4 a01 = *reinterpret_cast<const float4*>(xin + W_IN);
    const float4 a10 = *reinterpret_cast<const float4*>(xin + H_IN * W_IN);
    const float4 a11 = *reinterpret_cast<const float4*>(xin + H_IN * W_IN + W_IN);

    // ---- Block 0 (w pair .x,.y) ----
    // stage W
    float t0_00 = a00.x + a00.y, t1_00 = a00.x - a00.y;   // [d0][h0]
    float t0_01 = a01.x + a01.y, t1_01 = a01.x - a01.y;   // [d0][h1]
    float t0_10 = a10.x + a10.y, t1_10 = a10.x - a10.y;   // [d1][h0]
    float t0_11 = a11.x + a11.y, t1_11 = a11.x - a11.y;   // [d1][h1]
    // stage H: u[b][c][d]
    float u00_0 = t0_00 + t0_01, u10_0 = t0_00 - t0_01;
    float u01_0 = t1_00 + t1_01, u11_0 = t1_00 - t1_01;
    float u00_1 = t0_10 + t0_11, u10_1 = t0_10 - t0_11;
    float u01_1 = t1_10 + t1_11, u11_1 = t1_10 - t1_11;
    // stage D -> 8 outputs (block 0)
    float o0_b0 = (u00_0 + u00_1) * 0.125f;  // lll  o = a*4+b*2+c = 0
    float o1_b0 = (u01_0 + u01_1) * 0.125f;  // llh
    float o2_b0 = (u10_0 + u10_1) * 0.125f;  // lhl
    float o3_b0 = (u11_0 + u11_1) * 0.125f;  // lhh
    float o4_b0 = (u00_0 - u00_1) * 0.125f;  // hll
    float o5_b0 = (u01_0 - u01_1) * 0.125f;  // hlh
    float o6_b0 = (u10_0 - u10_1) * 0.125f;  // hhl
    float o7_b0 = (u11_0 - u11_1) * 0.125f;  // hhh

    // ---- Block 1 (w pair .z,.w) ----
    t0_00 = a00.z + a00.w; t1_00 = a00.z - a00.w;
    t0_01 = a01.z + a01.w; t1_01 = a01.z - a01.w;
    t0_10 = a10.z + a10.w; t1_10 = a10.z - a10.w;
    t0_11 = a11.z + a11.w; t1_11 = a11.z - a11.w;
    u00_0 = t0_00 + t0_01; u10_0 = t0_00 - t0_01;
    u01_0 = t1_00 + t1_01; u11_0 = t1_00 - t1_01;
    u00_1 = t0_10 + t0_11; u10_1 = t0_10 - t0_11;
    u01_1 = t1_10 + t1_11; u11_1 = t1_10 - t1_11;
    float o0_b1 = (u00_0 + u00_1) * 0.125f;
    float o1_b1 = (u01_0 + u01_1) * 0.125f;
    float o2_b1 = (u10_0 + u10_1) * 0.125f;
    float o3_b1 = (u11_0 + u11_1) * 0.125f;
    float o4_b1 = (u00_0 - u00_1) * 0.125f;
    float o5_b1 = (u01_0 - u01_1) * 0.125f;
    float o6_b1 = (u10_0 - u10_1) * 0.125f;
    float o7_b1 = (u11_0 - u11_1) * 0.125f;

    // Output base: y[n][c*8 + 0][d2][h2][2*w4]   (channel plane stride = 64^3)
    const size_t plane = (size_t)D2 * H2 * W2;   // 262144
    float* yo = y + (size_t)nc * 8 * plane
                  + (size_t)d2 * (H2 * W2)
                  + (size_t)h2 * W2
                  + 2 * w4;

    *reinterpret_cast<float2*>(yo + 0 * plane) = make_float2(o0_b0, o0_b1);
    *reinterpret_cast<float2*>(yo + 1 * plane) = make_float2(o1_b0, o1_b1);
    *reinterpret_cast<float2*>(yo + 2 * plane) = make_float2(o2_b0, o2_b1);
    *reinterpret_cast<float2*>(yo + 3 * plane) = make_float2(o3_b0, o3_b1);
    *reinterpret_cast<float2*>(yo + 4 * plane) = make_float2(o4_b0, o4_b1);
    *reinterpret_cast<float2*>(yo + 5 * plane) = make_float2(o5_b0, o5_b1);
    *reinterpret_cast<float2*>(yo + 6 * plane) = make_float2(o6_b0, o6_b1);
    *reinterpret_cast<float2*>(yo + 7 * plane) = make_float2(o7_b0, o7_b1);
}

extern "C" void kernel_launch(void* const* d_in, const int* in_sizes, int n_in,
                              void* d_out, int out_size)
{
    const float* x = (const float*)d_in[0];
    // d_in[1] is the fixed Haar filter bank; its values (+-0.125 products) are
    // hardcoded in the butterfly above.
    float* y = (float*)d_out;

    // grid.x = N*C*D2 = 2*16*64 = 2048 ; grid.y = H2/8 = 8 ; block = 32x8
    dim3 block(32, 8, 1);
    dim3 grid(2 * C_IN * D2, H2 / 8, 1);
    haar3d_kernel<<<grid, block>>>(x, y);
}

// round 4
// speedup vs baseline: 1.0076x; 1.0076x over previous
#include <cuda_runtime.h>
#include <cstdint>

// Haar 3D, stride-2, 2x2x2 depthwise, 8 filters per channel.
// x: [N=2, C=16, D=128, H=128, W=128] fp32
// y: [N=2, C*8=128, D2=64, H2=64, W2=64] fp32
//
// One thread processes FOUR adjacent 2x2x2 blocks along W:
//   loads:  8 x float4 streaming (2 depth planes x 2 rows x 8 consecutive w)
//   stores: 8 x float4 streaming (one per Haar output channel)
// Filter o = a*4 + b*2 + c (a: depth bit, b: height bit, c: width bit),
// y_o = 0.125 * sum_{ijk} (-1)^(a*i + b*j + c*k) v[i][j][k]  -- pure butterfly.

#define C_IN   16
#define D_IN   128
#define H_IN   128
#define W_IN   128
#define D2     64
#define H2     64
#define W2     64

__global__ __launch_bounds__(256) void haar3d_kernel(
    const float* __restrict__ x, float* __restrict__ y)
{
    const int wx  = threadIdx.x;                            // 0..15 (covers 4 w-blocks = 8 floats)
    const int h2  = blockIdx.y * blockDim.y + threadIdx.y;  // 0..63
    const int ncd = blockIdx.x;                             // n*C*D2 flat
    const int d2  = ncd & 63;
    const int nc  = ncd >> 6;                               // n*C + c

    // Input base: x[n][c][2*d2][2*h2][8*wx]
    const float* xin = x
        + ((size_t)nc * D_IN + 2 * d2) * (size_t)(H_IN * W_IN)
        + (size_t)(2 * h2) * W_IN
        + 8 * wx;

    // 8 vectorized streaming loads (front-batched for MLP)
    float4 v[2][2][2];   // [d][h][vec]
    #pragma unroll
    for (int dd = 0; dd < 2; dd++)
        #pragma unroll
        for (int hh = 0; hh < 2; hh++) {
            const float4* p = reinterpret_cast<const float4*>(
                xin + dd * (H_IN * W_IN) + hh * W_IN);
            v[dd][hh][0] = __ldcs(p);
            v[dd][hh][1] = __ldcs(p + 1);
        }

    float out[8][4];     // [channel][w-block]
    #pragma unroll
    for (int j = 0; j < 4; j++) {
        // w-pair j: floats (2j, 2j+1) of the 8-float row segment
        const float* f00 = reinterpret_cast<const float*>(&v[0][0][0]);
        const float* f01 = reinterpret_cast<const float*>(&v[0][1][0]);
        const float* f10 = reinterpret_cast<const float*>(&v[1][0][0]);
        const float* f11 = reinterpret_cast<const float*>(&v[1][1][0]);
        // stage W
        float t0_00 = f00[2*j] + f00[2*j+1], t1_00 = f00[2*j] - f00[2*j+1];
        float t0_01 = f01[2*j] + f01[2*j+1], t1_01 = f01[2*j] - f01[2*j+1];
        float t0_10 = f10[2*j] + f10[2*j+1], t1_10 = f10[2*j] - f10[2*j+1];
        float t0_11 = f11[2*j] + f11[2*j+1], t1_11 = f11[2*j] - f11[2*j+1];
        // stage H
        float u00_0 = t0_00 + t0_01, u10_0 = t0_00 - t0_01;
        float u01_0 = t1_00 + t1_01, u11_0 = t1_00 - t1_01;
        float u00_1 = t0_10 + t0_11, u10_1 = t0_10 - t0_11;
        float u01_1 = t1_10 + t1_11, u11_1 = t1_10 - t1_11;
        // stage D -> 8 channels
        out[0][j] = (u00_0 + u00_1) * 0.125f;  // lll
        out[1][j] = (u01_0 + u01_1) * 0.125f;  // llh
        out[2][j] = (u10_0 + u10_1) * 0.125f;  // lhl
        out[3][j] = (u11_0 + u11_1) * 0.125f;  // lhh
        out[4][j] = (u00_0 - u00_1) * 0.125f;  // hll
        out[5][j] = (u01_0 - u01_1) * 0.125f;  // hlh
        out[6][j] = (u10_0 - u10_1) * 0.125f;  // hhl
        out[7][j] = (u11_0 - u11_1) * 0.125f;  // hhh
    }

    // Output base: y[n][c*8 + ch][d2][h2][4*wx]  (channel plane stride = 64^3)
    const size_t plane = (size_t)D2 * H2 * W2;   // 262144
    float* yo = y + (size_t)nc * 8 * plane
                  + (size_t)d2 * (H2 * W2)
                  + (size_t)h2 * W2
                  + 4 * wx;

    #pragma unroll
    for (int ch = 0; ch < 8; ch++) {
        __stcs(reinterpret_cast<float4*>(yo + (size_t)ch * plane),
               make_float4(out[ch][0], out[ch][1], out[ch][2], out[ch][3]));
    }
}

extern "C" void kernel_launch(void* const* d_in, const int* in_sizes, int n_in,
                              void* d_out, int out_size)
{
    const float* x = (const float*)d_in[0];
    // d_in[1] is the fixed Haar filter bank; its values (+-0.125 products) are
    // hardcoded in the butterfly above.
    float* y = (float*)d_out;

    // grid.x = N*C*D2 = 2*16*64 = 2048 ; grid.y = H2/16 = 4 ; block = 16x16
    dim3 block(16, 16, 1);
    dim3 grid(2 * C_IN * D2, H2 / 16, 1);
    haar3d_kernel<<<grid, block>>>(x, y);
}